// round 8
// baseline (speedup 1.0000x reference)
#include <cuda_runtime.h>
#include <math.h>

#define TT 128
#define BB 128
#define DIN 3
#define HH 256
#define HID 512
#define GG 1024   // 4*H
#define KK 60
#define START_TAG 58
#define STOP_TAG 59
#define NEGV -10000.0f
#define NBLK 256  // persistent recurrent grid size (64 jtiles * 2 bh * 2 d)

// ---------------- packed f32x2 helpers (sm_103a FFMA2) ----------------
__device__ __forceinline__ unsigned long long pk2(float lo, float hi) {
    unsigned long long r;
    asm("mov.b64 %0, {%1, %2};" : "=l"(r) : "f"(lo), "f"(hi));
    return r;
}
__device__ __forceinline__ void upk2(unsigned long long v, float& lo, float& hi) {
    asm("mov.b64 {%0, %1}, %2;" : "=f"(lo), "=f"(hi) : "l"(v));
}
__device__ __forceinline__ void ffma2(unsigned long long& d, unsigned long long a,
                                      unsigned long long b) {
    asm("fma.rn.f32x2 %0, %1, %2, %0;" : "+l"(d) : "l"(a), "l"(b));
}

// ---------------- scratch (static device globals; no allocs allowed) ----------------
__device__ float d_wih1R[2 * GG * DIN];          // [d][j'][c]
__device__ float d_whhR[7 * 2 * HH * GG];        // [l][d][k][j']
__device__ float d_wihR[6 * 2 * HID * GG];       // [l-1][d][k][j']
__device__ float d_biasR[7 * 2 * GG];            // [l][d][j']
__device__ float d_xw[2 * TT * BB * GG];         // [d][t][b][j']  (134 MB)
__device__ float d_OA[TT * BB * HID];
__device__ float d_OB[TT * BB * HID];
__device__ float d_hbuf[2 * 2 * BB * HH];        // [parity][d][b][k]
__device__ float d_feats[TT * BB * KK];
__device__ unsigned int d_barc;                  // barrier arrive counter
__device__ unsigned int d_barg;                  // barrier generation

// ---------------- weight rearrangement: j' = hidx*4 + gate ----------------
__global__ void prep_layer1(const float* __restrict__ w_ih1,
                            const float* __restrict__ w_hh1,
                            const float* __restrict__ b1) {
    int idx = blockIdx.x * blockDim.x + threadIdx.x;
    if (idx < 2 * HH * GG) {
        int j = idx % GG;
        int k = (idx / GG) % HH;
        int d = idx / (GG * HH);
        int gate = j & 3, hidx = j >> 2;
        d_whhR[idx] = w_hh1[(d * GG + gate * HH + hidx) * HH + k];
    }
    if (idx < 2 * GG) {
        int j = idx % GG;
        int d = idx / GG;
        int gate = j & 3, hidx = j >> 2;
        d_biasR[idx] = b1[d * GG + gate * HH + hidx];
        for (int c = 0; c < DIN; c++)
            d_wih1R[(d * GG + j) * DIN + c] = w_ih1[(d * GG + gate * HH + hidx) * DIN + c];
    }
}

__global__ void prep_layers(const float* __restrict__ w_ih,
                            const float* __restrict__ w_hh,
                            const float* __restrict__ b) {
    int idx = blockIdx.x * blockDim.x + threadIdx.x;
    if (idx < 6 * 2 * HID * GG) {
        int j = idx % GG;
        int k = (idx / GG) % HID;
        int ld = idx / (GG * HID);   // li*2+d
        int gate = j & 3, hidx = j >> 2;
        d_wihR[idx] = w_ih[(ld * GG + gate * HH + hidx) * HID + k];
    }
    if (idx < 6 * 2 * HH * GG) {
        int j = idx % GG;
        int k = (idx / GG) % HH;
        int ld = idx / (GG * HH);
        int gate = j & 3, hidx = j >> 2;
        d_whhR[2 * HH * GG + idx] = w_hh[(ld * GG + gate * HH + hidx) * HH + k];
    }
    if (idx < 6 * 2 * GG) {
        int j = idx % GG;
        int ld = idx / GG;
        int gate = j & 3, hidx = j >> 2;
        d_biasR[2 * GG + idx] = b[ld * GG + gate * HH + hidx];
    }
}

// ---------------- layer-1 input projection (Din=3, trivial) ----------------
__global__ void xw1_kernel(const float* __restrict__ sent) {
    int idx = blockIdx.x * blockDim.x + threadIdx.x;
    if (idx >= 2 * TT * BB * GG) return;
    int j = idx % GG;
    int b = (idx / GG) % BB;
    int t = (idx / (GG * BB)) % TT;
    int d = idx / (GG * BB * TT);
    int ts = d ? (TT - 1 - t) : t;
    const float* xr = sent + (ts * BB + b) * DIN;
    const float* w = d_wih1R + (d * GG + j) * DIN;
    d_xw[idx] = d_biasR[d * GG + j] + xr[0] * w[0] + xr[1] * w[1] + xr[2] * w[2];
}

// ---------------- h0 load (parity 0) ----------------
__global__ void hc_init(const float* __restrict__ h0, int layer) {
    int idx = blockIdx.x * blockDim.x + threadIdx.x;
    if (idx >= 2 * BB * HH) return;
    d_hbuf[idx] = h0[layer * 2 * BB * HH + idx];
}

// ---------------- xw GEMM for layers 2..7: xw = relu(x1)(+relu(x2)) @ W_ih^T + b ----------------
// grid (128 t, 8 ntiles, 2 d), 256 threads; tile 128(b) x 128(j'), k-tile 16, 8x8/thread, FFMA2
__global__ void __launch_bounds__(256, 2) xw_gemm(int layer, int x1sel, int use2) {
    __shared__ float As[16][132];   // [k][b]  rows 528B (8B-aligned)
    __shared__ float Bs[16][128];   // [k][j]
    int t = blockIdx.x;
    int n0 = blockIdx.y * 128;
    int d = blockIdx.z;
    int tsrc = d ? (TT - 1 - t) : t;
    const float* x1 = (x1sel ? d_OB : d_OA) + tsrc * BB * HID;
    const float* x2 = (x1sel ? d_OA : d_OB) + tsrc * BB * HID;
    const float* wb = d_wihR + ((layer - 1) * 2 + d) * HID * GG;
    int tid = threadIdx.x;
    // packed accumulators: acc2[i][j] holds rows (ty*8+2i, ty*8+2i+1) x col (tx*8+j)
    unsigned long long acc2[4][8];
    const unsigned long long ZZ = 0ull;   // (0.f,0.f)
#pragma unroll
    for (int i = 0; i < 4; i++)
#pragma unroll
        for (int j = 0; j < 8; j++) acc2[i][j] = ZZ;
    int ty = tid >> 4;
    int tx = tid & 15;

    for (int k0 = 0; k0 < HID; k0 += 16) {
#pragma unroll
        for (int p = 0; p < 2; p++) {
            int f = p * 256 + tid;
            int b = f >> 2;
            int kq = f & 3;
            float4 v = *(const float4*)(x1 + b * HID + k0 + kq * 4);
            v.x = fmaxf(v.x, 0.f); v.y = fmaxf(v.y, 0.f);
            v.z = fmaxf(v.z, 0.f); v.w = fmaxf(v.w, 0.f);
            if (use2) {
                float4 u = *(const float4*)(x2 + b * HID + k0 + kq * 4);
                v.x += fmaxf(u.x, 0.f); v.y += fmaxf(u.y, 0.f);
                v.z += fmaxf(u.z, 0.f); v.w += fmaxf(u.w, 0.f);
            }
            As[kq * 4 + 0][b] = v.x;
            As[kq * 4 + 1][b] = v.y;
            As[kq * 4 + 2][b] = v.z;
            As[kq * 4 + 3][b] = v.w;
        }
#pragma unroll
        for (int p = 0; p < 2; p++) {
            int f = p * 256 + tid;
            int k = f >> 5;
            int j4 = f & 31;
            *(float4*)&Bs[k][j4 * 4] = *(const float4*)(wb + (k0 + k) * GG + n0 + j4 * 4);
        }
        __syncthreads();
#pragma unroll
        for (int k = 0; k < 16; k++) {
            // a row-pairs as packed b64 loads (8B aligned)
            unsigned long long ap[4];
#pragma unroll
            for (int i = 0; i < 4; i++)
                ap[i] = *(const unsigned long long*)&As[k][ty * 8 + 2 * i];
            float4 b0 = *(const float4*)&Bs[k][tx * 8];
            float4 b1 = *(const float4*)&Bs[k][tx * 8 + 4];
            unsigned long long bb[8];
            bb[0] = pk2(b0.x, b0.x); bb[1] = pk2(b0.y, b0.y);
            bb[2] = pk2(b0.z, b0.z); bb[3] = pk2(b0.w, b0.w);
            bb[4] = pk2(b1.x, b1.x); bb[5] = pk2(b1.y, b1.y);
            bb[6] = pk2(b1.z, b1.z); bb[7] = pk2(b1.w, b1.w);
#pragma unroll
            for (int i = 0; i < 4; i++)
#pragma unroll
                for (int j = 0; j < 8; j++) ffma2(acc2[i][j], ap[i], bb[j]);
        }
        __syncthreads();
    }
    float* outp = d_xw + ((d * TT + t) * BB) * GG + n0;
    const float* bias = d_biasR + (layer * 2 + d) * GG + n0;
    float bv[8];
#pragma unroll
    for (int jj = 0; jj < 8; jj++) bv[jj] = bias[tx * 8 + jj];
#pragma unroll
    for (int i = 0; i < 4; i++) {
#pragma unroll
        for (int half = 0; half < 2; half++) {
            int row = ty * 8 + 2 * i + half;
            float a[8];
#pragma unroll
            for (int jj = 0; jj < 8; jj++) {
                float lo, hi;
                upk2(acc2[i][jj], lo, hi);
                a[jj] = half ? hi : lo;
            }
            float4 o0, o1;
            o0.x = a[0] + bv[0]; o0.y = a[1] + bv[1];
            o0.z = a[2] + bv[2]; o0.w = a[3] + bv[3];
            o1.x = a[4] + bv[4]; o1.y = a[5] + bv[5];
            o1.z = a[6] + bv[6]; o1.w = a[7] + bv[7];
            *(float4*)(outp + row * GG + tx * 8) = o0;
            *(float4*)(outp + row * GG + tx * 8 + 4) = o1;
        }
    }
}

// ---------------- grid barrier (all NBLK blocks resident by construction) ----------------
__device__ __forceinline__ void grid_barrier() {
    __syncthreads();
    __threadfence();
    if (threadIdx.x == 0) {
        unsigned int gen = *((volatile unsigned int*)&d_barg);   // snapshot BEFORE arrive
        if (atomicAdd(&d_barc, 1u) == NBLK - 1) {
            d_barc = 0;
            __threadfence();
            atomicAdd(&d_barg, 1u);                              // release
        } else {
            while (*((volatile unsigned int*)&d_barg) == gen) __nanosleep(64);
        }
        __threadfence();
    }
    __syncthreads();
}

// ---------------- persistent per-layer recurrence: all 128 timesteps in one launch ----------------
// grid (64 jtiles, 2 bh, 2 d), 128 threads. W_hh slice in smem, c in registers, FFMA2 inner loop.
__global__ void __launch_bounds__(128, 2) rec_layer(int layer, int outsel,
                                                    const float* __restrict__ c0) {
    __shared__ float Ws[HH][16];    // [k][jloc]  16 KB, loaded once; rows 64B
    __shared__ float Hs[64][68];    // [k][b_local]  17.4 KB; rows 272B (8B-aligned)
    __shared__ float sg[64][17];    // gates per b_local
    int d = blockIdx.z;
    int bh = blockIdx.y;
    int j0 = blockIdx.x * 16;
    int tid = threadIdx.x;
    const float* wb = d_whhR + (layer * 2 + d) * HH * GG;

    // load W slice once: 256 k x 16 j = 1024 float4, 8 per thread
#pragma unroll
    for (int p = 0; p < 8; p++) {
        int f = p * 128 + tid;          // 0..1023
        int k = f >> 2;
        int j4 = (f & 3) * 4;
        *(float4*)&Ws[k][j4] = *(const float4*)(wb + k * GG + j0 + j4);
    }

    // cell-state registers: thread owns (b = tid&63, hl = (tid>>6)*2 + q)
    int cb = tid & 63;
    int hp = tid >> 6;
    int gb = bh * 64 + cb;
    float creg[2];
#pragma unroll
    for (int q = 0; q < 2; q++) {
        int hg = (j0 >> 2) + hp * 2 + q;
        creg[q] = c0[((layer * 2 + d) * BB + gb) * HH + hg];
    }
    __syncthreads();

    int jq = tid & 3;    // gemm cols jq*4..+3
    int bq = tid >> 2;   // gemm rows bq*2, bq*2+1
    float* outp = (outsel ? d_OB : d_OA);

    for (int t = 0; t < TT; t++) {
        int parity = t & 1;
        const float* hb = d_hbuf + parity * 2 * BB * HH + d * BB * HH + bh * 64 * HH;
        unsigned long long acc2[4];   // lanes = rows (bq*2, bq*2+1), idx = col jq*4+j
#pragma unroll
        for (int j = 0; j < 4; j++) acc2[j] = 0ull;

        for (int k0 = 0; k0 < HH; k0 += 64) {
#pragma unroll
            for (int p = 0; p < 8; p++) {   // Hs: 64b x 64k = 1024 float4
                int f = p * 128 + tid;
                int b = f >> 4;             // 0..63
                int kq = f & 15;            // 0..15 -> k = kq*4..+3
                float4 v = *(const float4*)(hb + b * HH + k0 + kq * 4);
                Hs[kq * 4 + 0][b] = v.x;
                Hs[kq * 4 + 1][b] = v.y;
                Hs[kq * 4 + 2][b] = v.z;
                Hs[kq * 4 + 3][b] = v.w;
            }
            __syncthreads();
#pragma unroll
            for (int k = 0; k < 64; k++) {
                unsigned long long hv2 = *(const unsigned long long*)&Hs[k][bq * 2];
                float4 w4 = *(const float4*)&Ws[k0 + k][jq * 4];
                ffma2(acc2[0], hv2, pk2(w4.x, w4.x));
                ffma2(acc2[1], hv2, pk2(w4.y, w4.y));
                ffma2(acc2[2], hv2, pk2(w4.z, w4.z));
                ffma2(acc2[3], hv2, pk2(w4.w, w4.w));
            }
            __syncthreads();
        }
        // gates = acc + xw
        const float* xwp = d_xw + ((d * TT + t) * BB + bh * 64) * GG + j0;
        {
            int b0r = bq * 2, b1r = bq * 2 + 1;
#pragma unroll
            for (int jj = 0; jj < 4; jj++) {
                float lo, hi;
                upk2(acc2[jj], lo, hi);
                sg[b0r][jq * 4 + jj] = lo + xwp[b0r * GG + jq * 4 + jj];
                sg[b1r][jq * 4 + jj] = hi + xwp[b1r * GG + jq * 4 + jj];
            }
        }
        __syncthreads();
        // cell update with register c
        int tout = d ? (TT - 1 - t) : t;
#pragma unroll
        for (int q = 0; q < 2; q++) {
            int hl = hp * 2 + q;
            float ig = sg[cb][hl * 4 + 0];
            float fg = sg[cb][hl * 4 + 1];
            float gg = sg[cb][hl * 4 + 2];
            float og = sg[cb][hl * 4 + 3];
            int hg = (j0 >> 2) + hl;
            float si = 1.f / (1.f + expf(-ig));
            float sf = 1.f / (1.f + expf(-fg));
            float so = 1.f / (1.f + expf(-og));
            float cn = sf * creg[q] + si * tanhf(gg);
            float hn = so * tanhf(cn);
            creg[q] = cn;
            d_hbuf[(parity ^ 1) * 2 * BB * HH + d * BB * HH + gb * HH + hg] = hn;
            outp[(tout * BB + gb) * HID + d * HH + hg] = hn;
        }
        if (t < TT - 1) grid_barrier();   // final step ordered by kernel boundary
    }
}

// ---------------- FC: feats = out @ fc_w^T + fc_b ----------------
__global__ void fc_kernel(const float* __restrict__ fc_w, const float* __restrict__ fc_b, int osel) {
    __shared__ float xs[8][HID];
    int r0 = blockIdx.x * 8;
    const float* O = osel ? d_OB : d_OA;
    int tid = threadIdx.x;   // 512
#pragma unroll
    for (int p = 0; p < 2; p++) {
        int f = p * 512 + tid;
        int r = f >> 7;
        int c = f & 127;
        *(float4*)&xs[r][c * 4] = *(const float4*)(O + (r0 + r) * HID + c * 4);
    }
    __syncthreads();
    int r = tid >> 6;
    int k = tid & 63;
    if (k < KK) {
        float acc = fc_b[k];
        const float* w = fc_w + k * HID;
#pragma unroll 8
        for (int c = 0; c < HID; c++) acc += xs[r][c] * w[c];
        d_feats[(r0 + r) * KK + k] = acc;
    }
}

// ---------------- CRF NLL: one block per batch element ----------------
__global__ void crf_kernel(const float* __restrict__ trans, const int* __restrict__ tags,
                           float* __restrict__ out) {
    __shared__ float tr[KK * KK];
    __shared__ float alpha[KK];
    __shared__ float red[64];
    int b = blockIdx.x;
    int tid = threadIdx.x;   // 64
    for (int i = tid; i < KK * KK; i += 64) tr[i] = trans[i];
    if (tid < KK) alpha[tid] = (tid == START_TAG) ? 0.f : NEGV;
    float gp = 0.f;
    for (int t = tid; t < TT; t += 64) {
        int tc = tags[t * BB + b];
        int tp = (t == 0) ? START_TAG : tags[(t - 1) * BB + b];
        gp += trans[tc * KK + tp] + d_feats[(t * BB + b) * KK + tc];
    }
    red[tid] = gp;
    __syncthreads();
    for (int t = 0; t < TT; t++) {
        float nv = 0.f;
        if (tid < KK) {
            const float* trow = tr + tid * KK;
            float m = -1e30f;
            for (int p = 0; p < KK; p++) m = fmaxf(m, alpha[p] + trow[p]);
            float s = 0.f;
            for (int p = 0; p < KK; p++) s += __expf(alpha[p] + trow[p] - m);
            nv = m + logf(s) + d_feats[(t * BB + b) * KK + tid];
        }
        __syncthreads();
        if (tid < KK) alpha[tid] = nv;
        __syncthreads();
    }
    if (tid == 0) {
        const float* trow = tr + STOP_TAG * KK;
        float m = -1e30f;
        for (int p = 0; p < KK; p++) m = fmaxf(m, alpha[p] + trow[p]);
        float s = 0.f;
        for (int p = 0; p < KK; p++) s += __expf(alpha[p] + trow[p] - m);
        float logz = m + logf(s);
        float gold = 0.f;
        for (int i = 0; i < 64; i++) gold += red[i];
        gold += trow[tags[(TT - 1) * BB + b]];
        out[b] = logz - gold;
    }
}

// ---------------- host orchestration ----------------
extern "C" void kernel_launch(void* const* d_in, const int* in_sizes, int n_in,
                              void* d_out, int out_size) {
    (void)in_sizes; (void)n_in; (void)out_size;
    const float* sentence = (const float*)d_in[0];
    const int*   tags     = (const int*)d_in[1];
    const float* w_ih1    = (const float*)d_in[2];
    const float* w_hh1    = (const float*)d_in[3];
    const float* b1       = (const float*)d_in[4];
    const float* w_ih     = (const float*)d_in[5];
    const float* w_hh     = (const float*)d_in[6];
    const float* b        = (const float*)d_in[7];
    const float* fc_w     = (const float*)d_in[8];
    const float* fc_b     = (const float*)d_in[9];
    const float* h0       = (const float*)d_in[10];
    const float* c0       = (const float*)d_in[11];
    const float* trans    = (const float*)d_in[12];
    float* out = (float*)d_out;

    prep_layer1<<<(2 * HH * GG + 255) / 256, 256>>>(w_ih1, w_hh1, b1);
    prep_layers<<<(6 * 2 * HID * GG + 255) / 256, 256>>>(w_ih, w_hh, b);
    xw1_kernel<<<(2 * TT * BB * GG + 255) / 256, 256>>>(sentence);

    // layer 1 -> OA
    hc_init<<<(2 * BB * HH + 255) / 256, 256>>>(h0, 0);
    rec_layer<<<dim3(64, 2, 2), 128>>>(0, /*outsel=*/0, c0);

    for (int l = 0; l < 6; l++) {
        int x1sel = l & 1;            // which buffer holds current relu input
        xw_gemm<<<dim3(128, 8, 2), 256>>>(l + 1, x1sel, l > 0 ? 1 : 0);
        hc_init<<<(2 * BB * HH + 255) / 256, 256>>>(h0, l + 1);
        int outsel = 1 - x1sel;       // write to the other buffer
        rec_layer<<<dim3(64, 2, 2), 128>>>(l + 1, outsel, c0);
    }

    // final bilstm out is in OA (outsel of l=5 is 0)
    fc_kernel<<<TT * BB / 8, 512>>>(fc_w, fc_b, /*osel=*/0);
    crf_kernel<<<BB, 64>>>(trans, tags, out);
}

// round 11
// speedup vs baseline: 1.0413x; 1.0413x over previous
#include <cuda_runtime.h>
#include <math.h>

#define TT 128
#define BB 128
#define DIN 3
#define HH 256
#define HID 512
#define GG 1024   // 4*H
#define KK 60
#define START_TAG 58
#define STOP_TAG 59
#define NEGV -10000.0f
#define GRPBLK 64   // blocks per barrier group (one (d,bh) pair)

// ---------------- packed f32x2 helpers (sm_103a FFMA2) ----------------
__device__ __forceinline__ unsigned long long pk2(float lo, float hi) {
    unsigned long long r;
    asm("mov.b64 %0, {%1, %2};" : "=l"(r) : "f"(lo), "f"(hi));
    return r;
}
__device__ __forceinline__ void upk2(unsigned long long v, float& lo, float& hi) {
    asm("mov.b64 {%0, %1}, %2;" : "=f"(lo), "=f"(hi) : "l"(v));
}
__device__ __forceinline__ void ffma2(unsigned long long& d, unsigned long long a,
                                      unsigned long long b) {
    asm("fma.rn.f32x2 %0, %1, %2, %0;" : "+l"(d) : "l"(a), "l"(b));
}

// ---------------- scratch (static device globals; no allocs allowed) ----------------
__device__ float d_wih1R[2 * GG * DIN];          // [d][j'][c]
__device__ float d_whhR[7 * 2 * HH * GG];        // [l][d][k][j']
__device__ float d_wihR[6 * 2 * HID * GG];       // [l-1][d][k][j']
__device__ float d_biasR[7 * 2 * GG];            // [l][d][j']
__device__ float d_xw[2 * TT * BB * GG];         // [d][t][b][j']  (134 MB)
__device__ float d_OA[TT * BB * HID];
__device__ float d_OB[TT * BB * HID];
__device__ float d_hbuf[2 * 2 * BB * HH];        // [parity][d][b][k]
__device__ float d_feats[TT * BB * KK];
__device__ unsigned int d_barc4[4];              // per-(d,bh) barrier arrive counters
__device__ unsigned int d_barg4[4];              // per-(d,bh) barrier generations

// ---------------- weight rearrangement: j' = hidx*4 + gate ----------------
__global__ void prep_layer1(const float* __restrict__ w_ih1,
                            const float* __restrict__ w_hh1,
                            const float* __restrict__ b1) {
    int idx = blockIdx.x * blockDim.x + threadIdx.x;
    if (idx < 2 * HH * GG) {
        int j = idx % GG;
        int k = (idx / GG) % HH;
        int d = idx / (GG * HH);
        int gate = j & 3, hidx = j >> 2;
        d_whhR[idx] = w_hh1[(d * GG + gate * HH + hidx) * HH + k];
    }
    if (idx < 2 * GG) {
        int j = idx % GG;
        int d = idx / GG;
        int gate = j & 3, hidx = j >> 2;
        d_biasR[idx] = b1[d * GG + gate * HH + hidx];
        for (int c = 0; c < DIN; c++)
            d_wih1R[(d * GG + j) * DIN + c] = w_ih1[(d * GG + gate * HH + hidx) * DIN + c];
    }
}

__global__ void prep_layers(const float* __restrict__ w_ih,
                            const float* __restrict__ w_hh,
                            const float* __restrict__ b) {
    int idx = blockIdx.x * blockDim.x + threadIdx.x;
    if (idx < 6 * 2 * HID * GG) {
        int j = idx % GG;
        int k = (idx / GG) % HID;
        int ld = idx / (GG * HID);   // li*2+d
        int gate = j & 3, hidx = j >> 2;
        d_wihR[idx] = w_ih[(ld * GG + gate * HH + hidx) * HID + k];
    }
    if (idx < 6 * 2 * HH * GG) {
        int j = idx % GG;
        int k = (idx / GG) % HH;
        int ld = idx / (GG * HH);
        int gate = j & 3, hidx = j >> 2;
        d_whhR[2 * HH * GG + idx] = w_hh[(ld * GG + gate * HH + hidx) * HH + k];
    }
    if (idx < 6 * 2 * GG) {
        int j = idx % GG;
        int ld = idx / GG;
        int gate = j & 3, hidx = j >> 2;
        d_biasR[2 * GG + idx] = b[ld * GG + gate * HH + hidx];
    }
}

// ---------------- layer-1 input projection (Din=3, trivial) ----------------
__global__ void xw1_kernel(const float* __restrict__ sent) {
    int idx = blockIdx.x * blockDim.x + threadIdx.x;
    if (idx >= 2 * TT * BB * GG) return;
    int j = idx % GG;
    int b = (idx / GG) % BB;
    int t = (idx / (GG * BB)) % TT;
    int d = idx / (GG * BB * TT);
    int ts = d ? (TT - 1 - t) : t;
    const float* xr = sent + (ts * BB + b) * DIN;
    const float* w = d_wih1R + (d * GG + j) * DIN;
    d_xw[idx] = d_biasR[d * GG + j] + xr[0] * w[0] + xr[1] * w[1] + xr[2] * w[2];
}

// ---------------- h0 load (parity 0) ----------------
__global__ void hc_init(const float* __restrict__ h0, int layer) {
    int idx = blockIdx.x * blockDim.x + threadIdx.x;
    if (idx >= 2 * BB * HH) return;
    d_hbuf[idx] = h0[layer * 2 * BB * HH + idx];
}

// ---------------- xw GEMM for layers 2..7: xw = relu(x1)(+relu(x2)) @ W_ih^T + b ----------------
// grid (128 t, 8 ntiles, 2 d), 256 threads; tile 128(b) x 128(j'), k-tile 16, 8x8/thread, FFMA2
__global__ void __launch_bounds__(256, 2) xw_gemm(int layer, int x1sel, int use2) {
    __shared__ float As[16][132];   // [k][b]  rows 528B (8B-aligned)
    __shared__ float Bs[16][128];   // [k][j]
    int t = blockIdx.x;
    int n0 = blockIdx.y * 128;
    int d = blockIdx.z;
    int tsrc = d ? (TT - 1 - t) : t;
    const float* x1 = (x1sel ? d_OB : d_OA) + tsrc * BB * HID;
    const float* x2 = (x1sel ? d_OA : d_OB) + tsrc * BB * HID;
    const float* wb = d_wihR + ((layer - 1) * 2 + d) * HID * GG;
    int tid = threadIdx.x;
    // packed accumulators: acc2[i][j] holds rows (ty*8+2i, ty*8+2i+1) x col (tx*8+j)
    unsigned long long acc2[4][8];
#pragma unroll
    for (int i = 0; i < 4; i++)
#pragma unroll
        for (int j = 0; j < 8; j++) acc2[i][j] = 0ull;
    int ty = tid >> 4;
    int tx = tid & 15;

    for (int k0 = 0; k0 < HID; k0 += 16) {
#pragma unroll
        for (int p = 0; p < 2; p++) {
            int f = p * 256 + tid;
            int b = f >> 2;
            int kq = f & 3;
            float4 v = *(const float4*)(x1 + b * HID + k0 + kq * 4);
            v.x = fmaxf(v.x, 0.f); v.y = fmaxf(v.y, 0.f);
            v.z = fmaxf(v.z, 0.f); v.w = fmaxf(v.w, 0.f);
            if (use2) {
                float4 u = *(const float4*)(x2 + b * HID + k0 + kq * 4);
                v.x += fmaxf(u.x, 0.f); v.y += fmaxf(u.y, 0.f);
                v.z += fmaxf(u.z, 0.f); v.w += fmaxf(u.w, 0.f);
            }
            As[kq * 4 + 0][b] = v.x;
            As[kq * 4 + 1][b] = v.y;
            As[kq * 4 + 2][b] = v.z;
            As[kq * 4 + 3][b] = v.w;
        }
#pragma unroll
        for (int p = 0; p < 2; p++) {
            int f = p * 256 + tid;
            int k = f >> 5;
            int j4 = f & 31;
            *(float4*)&Bs[k][j4 * 4] = *(const float4*)(wb + (k0 + k) * GG + n0 + j4 * 4);
        }
        __syncthreads();
#pragma unroll
        for (int k = 0; k < 16; k++) {
            // a row-pairs as packed b64 loads (8B aligned)
            unsigned long long ap[4];
#pragma unroll
            for (int i = 0; i < 4; i++)
                ap[i] = *(const unsigned long long*)&As[k][ty * 8 + 2 * i];
            float4 b0 = *(const float4*)&Bs[k][tx * 8];
            float4 b1 = *(const float4*)&Bs[k][tx * 8 + 4];
            unsigned long long bb[8];
            bb[0] = pk2(b0.x, b0.x); bb[1] = pk2(b0.y, b0.y);
            bb[2] = pk2(b0.z, b0.z); bb[3] = pk2(b0.w, b0.w);
            bb[4] = pk2(b1.x, b1.x); bb[5] = pk2(b1.y, b1.y);
            bb[6] = pk2(b1.z, b1.z); bb[7] = pk2(b1.w, b1.w);
#pragma unroll
            for (int i = 0; i < 4; i++)
#pragma unroll
                for (int j = 0; j < 8; j++) ffma2(acc2[i][j], ap[i], bb[j]);
        }
        __syncthreads();
    }
    float* outp = d_xw + ((d * TT + t) * BB) * GG + n0;
    const float* bias = d_biasR + (layer * 2 + d) * GG + n0;
    float bv[8];
#pragma unroll
    for (int jj = 0; jj < 8; jj++) bv[jj] = bias[tx * 8 + jj];
#pragma unroll
    for (int i = 0; i < 4; i++) {
#pragma unroll
        for (int half = 0; half < 2; half++) {
            int row = ty * 8 + 2 * i + half;
            float a[8];
#pragma unroll
            for (int jj = 0; jj < 8; jj++) {
                float lo, hi;
                upk2(acc2[i][jj], lo, hi);
                a[jj] = half ? hi : lo;
            }
            float4 o0, o1;
            o0.x = a[0] + bv[0]; o0.y = a[1] + bv[1];
            o0.z = a[2] + bv[2]; o0.w = a[3] + bv[3];
            o1.x = a[4] + bv[4]; o1.y = a[5] + bv[5];
            o1.z = a[6] + bv[6]; o1.w = a[7] + bv[7];
            *(float4*)(outp + row * GG + tx * 8) = o0;
            *(float4*)(outp + row * GG + tx * 8 + 4) = o1;
        }
    }
}

// ---------------- group barrier: 64 blocks of one (d,bh) pair ----------------
// Pure busy-poll (NO __nanosleep): nanosleep wakeup granularity is suspected to
// cost multiple us per step across 896 steps. Only thread 0 spins.
__device__ __forceinline__ void group_barrier(int gid) {
    __syncthreads();
    __threadfence();
    if (threadIdx.x == 0) {
        unsigned int gen = *((volatile unsigned int*)&d_barg4[gid]);   // snapshot BEFORE arrive
        if (atomicAdd(&d_barc4[gid], 1u) == GRPBLK - 1) {
            d_barc4[gid] = 0;
            __threadfence();
            atomicAdd(&d_barg4[gid], 1u);                              // release
        } else {
            while (*((volatile unsigned int*)&d_barg4[gid]) == gen) { }
        }
        __threadfence();
    }
    __syncthreads();
}

// ---------------- persistent per-layer recurrence: all 128 timesteps in one launch ----------------
// grid (64 jtiles, 2 bh, 2 d), 128 threads. W_hh slice in smem, c in registers, FFMA2 inner loop.
// Each block only depends on its (d,bh) group's h-writes -> per-group barrier (64 arrivals).
__global__ void __launch_bounds__(128, 2) rec_layer(int layer, int outsel,
                                                    const float* __restrict__ c0) {
    __shared__ float Ws[HH][16];    // [k][jloc]  16 KB, loaded once; rows 64B
    __shared__ float Hs[64][68];    // [k][b_local]  17.4 KB; rows 272B (8B-aligned)
    __shared__ float sg[64][17];    // gates per b_local
    int d = blockIdx.z;
    int bh = blockIdx.y;
    int gid = d * 2 + bh;
    int j0 = blockIdx.x * 16;
    int tid = threadIdx.x;
    const float* wb = d_whhR + (layer * 2 + d) * HH * GG;

    // load W slice once: 256 k x 16 j = 1024 float4, 8 per thread
#pragma unroll
    for (int p = 0; p < 8; p++) {
        int f = p * 128 + tid;          // 0..1023
        int k = f >> 2;
        int j4 = (f & 3) * 4;
        *(float4*)&Ws[k][j4] = *(const float4*)(wb + k * GG + j0 + j4);
    }

    // cell-state registers: thread owns (b = tid&63, hl = (tid>>6)*2 + q)
    int cb = tid & 63;
    int hp = tid >> 6;
    int gb = bh * 64 + cb;
    float creg[2];
#pragma unroll
    for (int q = 0; q < 2; q++) {
        int hg = (j0 >> 2) + hp * 2 + q;
        creg[q] = c0[((layer * 2 + d) * BB + gb) * HH + hg];
    }
    __syncthreads();

    int jq = tid & 3;    // gemm cols jq*4..+3
    int bq = tid >> 2;   // gemm rows bq*2, bq*2+1
    int b0r = bq * 2, b1r = bq * 2 + 1;
    float* outp = (outsel ? d_OB : d_OA);

    for (int t = 0; t < TT; t++) {
        int parity = t & 1;
        const float* hb = d_hbuf + parity * 2 * BB * HH + d * BB * HH + bh * 64 * HH;
        // prefetch this thread's xw gate slice early (hides DRAM latency)
        const float* xwp = d_xw + ((d * TT + t) * BB + bh * 64) * GG + j0;
        float4 xw0 = *(const float4*)(xwp + b0r * GG + jq * 4);
        float4 xw1 = *(const float4*)(xwp + b1r * GG + jq * 4);

        unsigned long long acc2[4];   // lanes = rows (b0r, b1r), idx = col jq*4+j
#pragma unroll
        for (int j = 0; j < 4; j++) acc2[j] = 0ull;

        for (int k0 = 0; k0 < HH; k0 += 64) {
#pragma unroll
            for (int p = 0; p < 8; p++) {   // Hs: 64b x 64k = 1024 float4
                int f = p * 128 + tid;
                int b = f >> 4;             // 0..63
                int kq = f & 15;            // 0..15 -> k = kq*4..+3
                float4 v = *(const float4*)(hb + b * HH + k0 + kq * 4);
                Hs[kq * 4 + 0][b] = v.x;
                Hs[kq * 4 + 1][b] = v.y;
                Hs[kq * 4 + 2][b] = v.z;
                Hs[kq * 4 + 3][b] = v.w;
            }
            __syncthreads();
#pragma unroll
            for (int k = 0; k < 64; k++) {
                unsigned long long hv2 = *(const unsigned long long*)&Hs[k][bq * 2];
                float4 w4 = *(const float4*)&Ws[k0 + k][jq * 4];
                ffma2(acc2[0], hv2, pk2(w4.x, w4.x));
                ffma2(acc2[1], hv2, pk2(w4.y, w4.y));
                ffma2(acc2[2], hv2, pk2(w4.z, w4.z));
                ffma2(acc2[3], hv2, pk2(w4.w, w4.w));
            }
            __syncthreads();
        }
        // gates = acc + xw (prefetched)
        {
            float xlo[4] = {xw0.x, xw0.y, xw0.z, xw0.w};
            float xhi[4] = {xw1.x, xw1.y, xw1.z, xw1.w};
#pragma unroll
            for (int jj = 0; jj < 4; jj++) {
                float lo, hi;
                upk2(acc2[jj], lo, hi);
                sg[b0r][jq * 4 + jj] = lo + xlo[jj];
                sg[b1r][jq * 4 + jj] = hi + xhi[jj];
            }
        }
        __syncthreads();
        // cell update with register c
        int tout = d ? (TT - 1 - t) : t;
#pragma unroll
        for (int q = 0; q < 2; q++) {
            int hl = hp * 2 + q;
            float ig = sg[cb][hl * 4 + 0];
            float fg = sg[cb][hl * 4 + 1];
            float gg = sg[cb][hl * 4 + 2];
            float og = sg[cb][hl * 4 + 3];
            int hg = (j0 >> 2) + hl;
            float si = 1.f / (1.f + expf(-ig));
            float sf = 1.f / (1.f + expf(-fg));
            float so = 1.f / (1.f + expf(-og));
            float cn = sf * creg[q] + si * tanhf(gg);
            float hn = so * tanhf(cn);
            creg[q] = cn;
            d_hbuf[(parity ^ 1) * 2 * BB * HH + d * BB * HH + gb * HH + hg] = hn;
            outp[(tout * BB + gb) * HID + d * HH + hg] = hn;
        }
        if (t < TT - 1) group_barrier(gid);   // final step ordered by kernel boundary
    }
}

// ---------------- FC: feats = out @ fc_w^T + fc_b ----------------
__global__ void fc_kernel(const float* __restrict__ fc_w, const float* __restrict__ fc_b, int osel) {
    __shared__ float xs[8][HID];
    int r0 = blockIdx.x * 8;
    const float* O = osel ? d_OB : d_OA;
    int tid = threadIdx.x;   // 512
#pragma unroll
    for (int p = 0; p < 2; p++) {
        int f = p * 512 + tid;
        int r = f >> 7;
        int c = f & 127;
        *(float4*)&xs[r][c * 4] = *(const float4*)(O + (r0 + r) * HID + c * 4);
    }
    __syncthreads();
    int r = tid >> 6;
    int k = tid & 63;
    if (k < KK) {
        float acc = fc_b[k];
        const float* w = fc_w + k * HID;
#pragma unroll 8
        for (int c = 0; c < HID; c++) acc += xs[r][c] * w[c];
        d_feats[(r0 + r) * KK + k] = acc;
    }
}

// ---------------- CRF NLL: one block per batch element ----------------
__global__ void crf_kernel(const float* __restrict__ trans, const int* __restrict__ tags,
                           float* __restrict__ out) {
    __shared__ float tr[KK * KK];
    __shared__ float alpha[KK];
    __shared__ float red[64];
    int b = blockIdx.x;
    int tid = threadIdx.x;   // 64
    for (int i = tid; i < KK * KK; i += 64) tr[i] = trans[i];
    if (tid < KK) alpha[tid] = (tid == START_TAG) ? 0.f : NEGV;
    float gp = 0.f;
    for (int t = tid; t < TT; t += 64) {
        int tc = tags[t * BB + b];
        int tp = (t == 0) ? START_TAG : tags[(t - 1) * BB + b];
        gp += trans[tc * KK + tp] + d_feats[(t * BB + b) * KK + tc];
    }
    red[tid] = gp;
    __syncthreads();
    for (int t = 0; t < TT; t++) {
        float nv = 0.f;
        if (tid < KK) {
            const float* trow = tr + tid * KK;
            float m = -1e30f;
            for (int p = 0; p < KK; p++) m = fmaxf(m, alpha[p] + trow[p]);
            float s = 0.f;
            for (int p = 0; p < KK; p++) s += __expf(alpha[p] + trow[p] - m);
            nv = m + logf(s) + d_feats[(t * BB + b) * KK + tid];
        }
        __syncthreads();
        if (tid < KK) alpha[tid] = nv;
        __syncthreads();
    }
    if (tid == 0) {
        const float* trow = tr + STOP_TAG * KK;
        float m = -1e30f;
        for (int p = 0; p < KK; p++) m = fmaxf(m, alpha[p] + trow[p]);
        float s = 0.f;
        for (int p = 0; p < KK; p++) s += __expf(alpha[p] + trow[p] - m);
        float logz = m + logf(s);
        float gold = 0.f;
        for (int i = 0; i < 64; i++) gold += red[i];
        gold += trow[tags[(TT - 1) * BB + b]];
        out[b] = logz - gold;
    }
}

// ---------------- host orchestration ----------------
extern "C" void kernel_launch(void* const* d_in, const int* in_sizes, int n_in,
                              void* d_out, int out_size) {
    (void)in_sizes; (void)n_in; (void)out_size;
    const float* sentence = (const float*)d_in[0];
    const int*   tags     = (const int*)d_in[1];
    const float* w_ih1    = (const float*)d_in[2];
    const float* w_hh1    = (const float*)d_in[3];
    const float* b1       = (const float*)d_in[4];
    const float* w_ih     = (const float*)d_in[5];
    const float* w_hh     = (const float*)d_in[6];
    const float* b        = (const float*)d_in[7];
    const float* fc_w     = (const float*)d_in[8];
    const float* fc_b     = (const float*)d_in[9];
    const float* h0       = (const float*)d_in[10];
    const float* c0       = (const float*)d_in[11];
    const float* trans    = (const float*)d_in[12];
    float* out = (float*)d_out;

    // Launch order chosen so the 4th launch (= ncu's sampled slot per R6/R8
    // observation) is rec_layer(0). prep_layers is only needed from layer 2 on.
    prep_layer1<<<(2 * HH * GG + 255) / 256, 256>>>(w_ih1, w_hh1, b1);           // 1
    xw1_kernel<<<(2 * TT * BB * GG + 255) / 256, 256>>>(sentence);               // 2
    hc_init<<<(2 * BB * HH + 255) / 256, 256>>>(h0, 0);                          // 3
    rec_layer<<<dim3(64, 2, 2), 128>>>(0, /*outsel=*/0, c0);                     // 4 <- profiled
    prep_layers<<<(6 * 2 * HID * GG + 255) / 256, 256>>>(w_ih, w_hh, b);         // 5

    for (int l = 0; l < 6; l++) {
        int x1sel = l & 1;            // which buffer holds current relu input
        xw_gemm<<<dim3(128, 8, 2), 256>>>(l + 1, x1sel, l > 0 ? 1 : 0);
        hc_init<<<(2 * BB * HH + 255) / 256, 256>>>(h0, l + 1);
        int outsel = 1 - x1sel;       // write to the other buffer
        rec_layer<<<dim3(64, 2, 2), 128>>>(l + 1, outsel, c0);
    }

    // final bilstm out is in OA (outsel of l=5 is 0)
    fc_kernel<<<TT * BB / 8, 512>>>(fc_w, fc_b, /*osel=*/0);
    crf_kernel<<<BB, 64>>>(trans, tags, out);
}